// round 8
// baseline (speedup 1.0000x reference)
#include <cuda_runtime.h>
#include <cuda_bf16.h>
#include <cstdint>

// DGCRM: after dead-code elimination, output = GRU cell over 16384 rows:
//   c = [h(64), x(2)]  (permuted combined vector, 66 wide)
//   z = sigmoid(c @ Wz + bz); r = sigmoid(c @ Wr + br)
//   cand = [r*h, x];  hc = tanh(cand @ Wc + bc)
//   out = z*h + (1-z)*hc
//
// R6 -> R7: smem crossbar was the real bottleneck (L1 46%). Transposed warp
// mapping: warp = 32 rows x 16 cols, lane = 1 row. Weight LDS are warp-uniform
// broadcasts; A read from transposed stride-33 tile (conflict-free, LDS imm
// offsets). Wc via warp-uniform LDG (L1-shared across CTAs) -> smem 42.5KB ->
// 5 CTAs/SM -> grid 512 fully resident, single wave.

#define CIN 66
#define HIDD 64
#define RPB 32
#define TPB 128
#define ATS 33   // transposed A-tile stride (conflict-free, odd)

__device__ __align__(16) float g_Wf[3 * CIN * HIDD];  // [m][j][col], j permuted [h..,x]
__device__ __align__(16) float g_Bf[3 * HIDD];

__device__ __forceinline__ unsigned long long pk2(float a, float b) {
    unsigned long long r;
    asm("mov.b64 %0, {%1, %2};" : "=l"(r) : "f"(a), "f"(b));
    return r;
}
__device__ __forceinline__ void upk2(unsigned long long v, float& a, float& b) {
    asm("mov.b64 {%0, %1}, %2;" : "=f"(a), "=f"(b) : "l"(v));
}
__device__ __forceinline__ void fma2(unsigned long long& d, unsigned long long a, unsigned long long b) {
    asm("fma.rn.f32x2 %0, %1, %2, %0;" : "+l"(d) : "l"(a), "l"(b));
}
__device__ __forceinline__ float fsig(float v) { return 1.f / (1.f + __expf(-v)); }
__device__ __forceinline__ float ftanh(float v) { return 1.f - 2.f / (__expf(2.f * v) + 1.f); }

// Fold rnn_W[6,198,64] -> 3 effective [66,64] matrices + biases, with row
// permutation (combined [x,h] order -> stored [h,x] order).
__global__ void fold_kernel(const float* __restrict__ W, const float* __restrict__ bvec) {
    int idx = blockIdx.x * blockDim.x + threadIdx.x;
    if (idx < 3 * CIN * HIDD) {
        int m = idx / (CIN * HIDD);
        int rem = idx - m * (CIN * HIDD);
        int j = rem / HIDD;
        int col = rem - j * HIDD;
        int k = (j < HIDD) ? (j + 2) : (j - HIDD);
        float s = 0.f;
#pragma unroll
        for (int t = 0; t < 2; ++t) {
            const float* base = W + (size_t)(2 * m + t) * 198 * HIDD + col;
            s += base[(size_t)k * HIDD]
               + 0.05f * (base[(size_t)(66 + k) * HIDD] + base[(size_t)(132 + k) * HIDD]);
        }
        g_Wf[idx] = s;
    }
    if (idx < 3 * HIDD) {
        int m = idx / HIDD, j = idx - m * HIDD;
        g_Bf[idx] = bvec[(2 * m) * HIDD + j] + bvec[(2 * m + 1) * HIDD + j];
    }
}

// Block: 32 rows, 4 warps (one 16-col group each). Lane = row.
__global__ void __launch_bounds__(TPB, 5) dgcrm_main(
    const float* __restrict__ x, const float* __restrict__ h0, float* __restrict__ out)
{
    extern __shared__ float sm[];
    float* Wsm = sm;                        // Wz,Wr: 2*66*64 = 8448 floats
    float* At  = Wsm + 2 * CIN * HIDD;      // 66*33 = 2178 floats (transposed A / out restage)

    const int tid  = threadIdx.x;
    const int lane = tid & 31;
    const int c0   = (tid >> 5) * 16;       // this warp's column group
    const int g0   = blockIdx.x * RPB;

    // Stage Wz,Wr (m=0,1 are first in g_Wf): straight float4 copy.
    for (int i = tid; i < 2 * CIN * 16; i += TPB) {
        ((float4*)Wsm)[i] = ((const float4*)g_Wf)[i];
    }
    // Stage A transposed: At[c][r] for c in 0..63 (h) and 64,65 (x).
#pragma unroll
    for (int it = 0; it < 4; ++it) {
        int i = tid + TPB * it;             // 0..511
        int r = i >> 4, q4 = i & 15;
        float4 v = *(const float4*)(h0 + (size_t)(g0 + r) * HIDD + q4 * 4);
        At[(q4 * 4 + 0) * ATS + r] = v.x;
        At[(q4 * 4 + 1) * ATS + r] = v.y;
        At[(q4 * 4 + 2) * ATS + r] = v.z;
        At[(q4 * 4 + 3) * ATS + r] = v.w;
    }
    if (tid < RPB) {
        float2 v = *(const float2*)(x + (size_t)(g0 + tid) * 2);
        At[64 * ATS + tid] = v.x;
        At[65 * ATS + tid] = v.y;
    }
    __syncthreads();

    unsigned long long zacc[8], racc[8];
#pragma unroll
    for (int i = 0; i < 8; ++i) { zacc[i] = 0ull; racc[i] = 0ull; }

    // ---- phase 1: z,r GEMMs. Weight LDS are warp-uniform broadcasts. ----
#pragma unroll 6
    for (int j = 0; j < CIN; ++j) {
        float a = At[j * ATS + lane];
        unsigned long long ap = pk2(a, a);
        const ulonglong2* wz = (const ulonglong2*)(Wsm + j * HIDD + c0);
        const ulonglong2* wr = (const ulonglong2*)(Wsm + CIN * HIDD + j * HIDD + c0);
        ulonglong2 u;
        u = wz[0]; fma2(zacc[0], ap, u.x); fma2(zacc[1], ap, u.y);
        u = wz[1]; fma2(zacc[2], ap, u.x); fma2(zacc[3], ap, u.y);
        u = wz[2]; fma2(zacc[4], ap, u.x); fma2(zacc[5], ap, u.y);
        u = wz[3]; fma2(zacc[6], ap, u.x); fma2(zacc[7], ap, u.y);
        u = wr[0]; fma2(racc[0], ap, u.x); fma2(racc[1], ap, u.y);
        u = wr[1]; fma2(racc[2], ap, u.x); fma2(racc[3], ap, u.y);
        u = wr[2]; fma2(racc[4], ap, u.x); fma2(racc[5], ap, u.y);
        u = wr[3]; fma2(racc[6], ap, u.x); fma2(racc[7], ap, u.y);
    }
    __syncthreads();   // all phase-1 A reads complete before candidate writes

    // ---- candidate: At[c][lane] = sigmoid(r + br) * h; keep h for epilogue ----
    float hsv[16];
    {
        const float4* bp = (const float4*)(g_Bf + HIDD + c0);
        float4 b0 = bp[0], b1 = bp[1], b2 = bp[2], b3 = bp[3];
        float rb[16] = { b0.x, b0.y, b0.z, b0.w, b1.x, b1.y, b1.z, b1.w,
                         b2.x, b2.y, b2.z, b2.w, b3.x, b3.y, b3.z, b3.w };
#pragma unroll
        for (int i = 0; i < 8; ++i) {
            float r0, r1;
            upk2(racc[i], r0, r1);
            int c = c0 + 2 * i;
            float ha = At[c * ATS + lane];
            float hb = At[(c + 1) * ATS + lane];
            hsv[2 * i]     = ha;
            hsv[2 * i + 1] = hb;
            At[c * ATS + lane]       = fsig(r0 + rb[2 * i]) * ha;
            At[(c + 1) * ATS + lane] = fsig(r1 + rb[2 * i + 1]) * hb;
        }
    }
    __syncthreads();

    // ---- phase 2: hc GEMM. Wc via warp-uniform LDG (L1-shared, not smem). ----
    unsigned long long cacc[8];
#pragma unroll
    for (int i = 0; i < 8; ++i) cacc[i] = 0ull;
#pragma unroll 6
    for (int j = 0; j < CIN; ++j) {
        float a = At[j * ATS + lane];
        unsigned long long ap = pk2(a, a);
        const ulonglong2* wc = (const ulonglong2*)(g_Wf + 2 * CIN * HIDD + j * HIDD + c0);
        ulonglong2 u;
        u = wc[0]; fma2(cacc[0], ap, u.x); fma2(cacc[1], ap, u.y);
        u = wc[1]; fma2(cacc[2], ap, u.x); fma2(cacc[3], ap, u.y);
        u = wc[2]; fma2(cacc[4], ap, u.x); fma2(cacc[5], ap, u.y);
        u = wc[3]; fma2(cacc[6], ap, u.x); fma2(cacc[7], ap, u.y);
    }
    __syncthreads();   // all phase-2 A reads done before restage overwrite

    // ---- epilogue: o = z*h + (1-z)*hc, written transposed into At ----
    {
        const float4* bzp = (const float4*)(g_Bf + c0);
        const float4* bcp = (const float4*)(g_Bf + 2 * HIDD + c0);
        float4 z0 = bzp[0], z1 = bzp[1], z2 = bzp[2], z3 = bzp[3];
        float4 c0v = bcp[0], c1v = bcp[1], c2v = bcp[2], c3v = bcp[3];
        float bz[16] = { z0.x, z0.y, z0.z, z0.w, z1.x, z1.y, z1.z, z1.w,
                         z2.x, z2.y, z2.z, z2.w, z3.x, z3.y, z3.z, z3.w };
        float bc[16] = { c0v.x, c0v.y, c0v.z, c0v.w, c1v.x, c1v.y, c1v.z, c1v.w,
                         c2v.x, c2v.y, c2v.z, c2v.w, c3v.x, c3v.y, c3v.z, c3v.w };
#pragma unroll
        for (int i = 0; i < 8; ++i) {
            float za, zb, ca, cb;
            upk2(zacc[i], za, zb);
            upk2(cacc[i], ca, cb);
            za = fsig(za + bz[2 * i]);
            zb = fsig(zb + bz[2 * i + 1]);
            ca = ftanh(ca + bc[2 * i]);
            cb = ftanh(cb + bc[2 * i + 1]);
            int c = c0 + 2 * i;
            At[c * ATS + lane]       = za * hsv[2 * i]     + (1.f - za) * ca;
            At[(c + 1) * ATS + lane] = zb * hsv[2 * i + 1] + (1.f - zb) * cb;
        }
    }
    __syncthreads();

    // ---- coalesced float4 stores ----
#pragma unroll
    for (int it = 0; it < 4; ++it) {
        int i = tid + TPB * it;
        int r = i >> 4, q4 = i & 15;
        float4 v;
        v.x = At[(q4 * 4 + 0) * ATS + r];
        v.y = At[(q4 * 4 + 1) * ATS + r];
        v.z = At[(q4 * 4 + 2) * ATS + r];
        v.w = At[(q4 * 4 + 3) * ATS + r];
        *(float4*)(out + (size_t)(g0 + r) * HIDD + q4 * 4) = v;
    }
}

static const int SMEM_BYTES = (2 * CIN * HIDD + CIN * ATS + 16) * 4;  // ~42.6 KB

extern "C" void kernel_launch(void* const* d_in, const int* in_sizes, int n_in,
                              void* d_out, int out_size) {
    (void)in_sizes; (void)n_in; (void)out_size;
    const float* x    = (const float*)d_in[0];    // [16,1024,2]
    const float* h0   = (const float*)d_in[1];    // [16,1024,64]
    const float* rnnW = (const float*)d_in[12];   // [6,198,64]
    const float* rnnb = (const float*)d_in[13];   // [6,64]
    float* out = (float*)d_out;                   // [16,1024,64]

    cudaFuncSetAttribute(dgcrm_main, cudaFuncAttributeMaxDynamicSharedMemorySize, SMEM_BYTES);

    fold_kernel<<<(3 * CIN * HIDD + 255) / 256, 256>>>(rnnW, rnnb);
    dgcrm_main<<<16384 / RPB, TPB, SMEM_BYTES>>>(x, h0, out);
}

// round 11
// speedup vs baseline: 1.0570x; 1.0570x over previous
#include <cuda_runtime.h>
#include <cuda_bf16.h>
#include <cstdint>

// DGCRM: after dead-code elimination, output = GRU cell over 16384 rows:
//   c = [h(64), x(2)]  (permuted combined vector, 66 wide)
//   z = sigmoid(c @ Wz + bz); r = sigmoid(c @ Wr + br)
//   cand = [r*h, x];  hc = tanh(cand @ Wc + bc)
//   out = z*h + (1-z)*hc
//
// R8 -> R9: issue-count-bound model. Thread tile 4 rows x 8 cols; per j:
// 4 weight LDS.128 + amortized 1 a-LDS.128 + 4 splats + 32 fma2 (78% useful).
// grid=256 (>=152 SMs), 2 CTAs/SM (smem 85.5KB), candidate in separate smem
// buffer, warp-local syncs only between GEMM phases.

#define CIN 66
#define HIDD 64
#define RPB 64
#define TPB 128
#define ASTR 68

__device__ __align__(16) float g_Wf[3 * CIN * HIDD];  // [m][j][col], j permuted [h..,x]
__device__ __align__(16) float g_Bf[3 * HIDD];

__device__ __forceinline__ unsigned long long pk2(float a, float b) {
    unsigned long long r;
    asm("mov.b64 %0, {%1, %2};" : "=l"(r) : "f"(a), "f"(b));
    return r;
}
__device__ __forceinline__ void upk2(unsigned long long v, float& a, float& b) {
    asm("mov.b64 {%0, %1}, %2;" : "=f"(a), "=f"(b) : "l"(v));
}
__device__ __forceinline__ void fma2(unsigned long long& d, unsigned long long a, unsigned long long b) {
    asm("fma.rn.f32x2 %0, %1, %2, %0;" : "+l"(d) : "l"(a), "l"(b));
}
__device__ __forceinline__ float fsig(float v) { return 1.f / (1.f + __expf(-v)); }
__device__ __forceinline__ float ftanh(float v) { return 1.f - 2.f / (__expf(2.f * v) + 1.f); }

// Fold rnn_W[6,198,64] -> 3 effective [66,64] matrices + biases, with row
// permutation (combined [x,h] order -> stored [h,x] order).
__global__ void fold_kernel(const float* __restrict__ W, const float* __restrict__ bvec) {
    int idx = blockIdx.x * blockDim.x + threadIdx.x;
    if (idx < 3 * CIN * HIDD) {
        int m = idx / (CIN * HIDD);
        int rem = idx - m * (CIN * HIDD);
        int j = rem / HIDD;
        int col = rem - j * HIDD;
        int k = (j < HIDD) ? (j + 2) : (j - HIDD);
        float s = 0.f;
#pragma unroll
        for (int t = 0; t < 2; ++t) {
            const float* base = W + (size_t)(2 * m + t) * 198 * HIDD + col;
            s += base[(size_t)k * HIDD]
               + 0.05f * (base[(size_t)(66 + k) * HIDD] + base[(size_t)(132 + k) * HIDD]);
        }
        g_Wf[idx] = s;
    }
    if (idx < 3 * HIDD) {
        int m = idx / HIDD, j = idx - m * HIDD;
        g_Bf[idx] = bvec[(2 * m) * HIDD + j] + bvec[(2 * m + 1) * HIDD + j];
    }
}

// Block: 64 rows x 64 cols, 128 threads. Thread: 4 rows x 8 cols.
// tx = tid&7 -> cols c0=8*tx; ty = tid>>3 -> rows 4*ty.
__global__ void __launch_bounds__(TPB) dgcrm_main(
    const float* __restrict__ x, const float* __restrict__ h0, float* __restrict__ out)
{
    extern __shared__ float sm[];
    float* Wsm = sm;                        // 3*66*64 = 12672 floats
    float* As  = Wsm + 3 * CIN * HIDD;      // 64*68 = 4352 (original [h,x])
    float* Ac  = As + RPB * ASTR;           // 64*68 (candidate [r*h, x])

    const int tid = threadIdx.x;
    const int tx = tid & 7;
    const int ty = tid >> 3;
    const int c0 = tx * 8;
    const int rowbase = ty * 4;
    const int g0 = blockIdx.x * RPB;

    // Stage all three weight matrices (pre-folded, pre-permuted).
    for (int i = tid; i < 3 * CIN * 16; i += TPB)
        ((float4*)Wsm)[i] = ((const float4*)g_Wf)[i];

    // Stage A: h into As[:,0:64]; x into both As and Ac cols 64..65.
    for (int i = tid; i < RPB * 16; i += TPB) {
        int r = i >> 4, c = i & 15;
        float4 v = *(const float4*)(h0 + (size_t)(g0 + r) * HIDD + c * 4);
        *(float4*)(As + r * ASTR + c * 4) = v;
    }
    if (tid < RPB) {
        float2 v = *(const float2*)(x + (size_t)(g0 + tid) * 2);
        As[tid * ASTR + 64] = v.x;  As[tid * ASTR + 65] = v.y;
        Ac[tid * ASTR + 64] = v.x;  Ac[tid * ASTR + 65] = v.y;
    }
    __syncthreads();

    const float* Wz = Wsm;
    const float* Wr = Wsm + CIN * HIDD;
    const float* Wc = Wsm + 2 * CIN * HIDD;

    unsigned long long zacc[4][4], racc[4][4];
#pragma unroll
    for (int rr = 0; rr < 4; rr++)
#pragma unroll
        for (int q = 0; q < 4; q++) { zacc[rr][q] = 0ull; racc[rr][q] = 0ull; }

    // ---- phase 1: z,r GEMMs over h-cols (j = 0..63), a batched per 4 j ----
#pragma unroll 2
    for (int j4 = 0; j4 < 16; ++j4) {
        float av[4][4];
#pragma unroll
        for (int rr = 0; rr < 4; rr++) {
            float4 q = *(const float4*)(As + (rowbase + rr) * ASTR + j4 * 4);
            av[rr][0] = q.x; av[rr][1] = q.y; av[rr][2] = q.z; av[rr][3] = q.w;
        }
#pragma unroll
        for (int k = 0; k < 4; ++k) {
            const int j = j4 * 4 + k;
            const ulonglong2* wzp = (const ulonglong2*)(Wz + j * HIDD + c0);
            const ulonglong2* wrp = (const ulonglong2*)(Wr + j * HIDD + c0);
            const ulonglong2 z0 = wzp[0], z1 = wzp[1];
            const ulonglong2 r0 = wrp[0], r1 = wrp[1];
#pragma unroll
            for (int rr = 0; rr < 4; rr++) {
                const unsigned long long ap = pk2(av[rr][k], av[rr][k]);
                fma2(zacc[rr][0], ap, z0.x); fma2(zacc[rr][1], ap, z0.y);
                fma2(zacc[rr][2], ap, z1.x); fma2(zacc[rr][3], ap, z1.y);
                fma2(racc[rr][0], ap, r0.x); fma2(racc[rr][1], ap, r0.y);
                fma2(racc[rr][2], ap, r1.x); fma2(racc[rr][3], ap, r1.y);
            }
        }
    }
    // tail: x-cols j = 64, 65
#pragma unroll
    for (int j = 64; j < 66; ++j) {
        const ulonglong2* wzp = (const ulonglong2*)(Wz + j * HIDD + c0);
        const ulonglong2* wrp = (const ulonglong2*)(Wr + j * HIDD + c0);
        const ulonglong2 z0 = wzp[0], z1 = wzp[1];
        const ulonglong2 r0 = wrp[0], r1 = wrp[1];
#pragma unroll
        for (int rr = 0; rr < 4; rr++) {
            float a = As[(rowbase + rr) * ASTR + j];
            const unsigned long long ap = pk2(a, a);
            fma2(zacc[rr][0], ap, z0.x); fma2(zacc[rr][1], ap, z0.y);
            fma2(zacc[rr][2], ap, z1.x); fma2(zacc[rr][3], ap, z1.y);
            fma2(racc[rr][0], ap, r0.x); fma2(racc[rr][1], ap, r0.y);
            fma2(racc[rr][2], ap, r1.x); fma2(racc[rr][3], ap, r1.y);
        }
    }
    // Rows rowbase..rowbase+3 in As/Ac are touched only by this warp's
    // threads (same ty group lives in one warp) -> warp sync suffices.
    __syncwarp();

    // ---- candidate: Ac[r][c] = sigmoid(r + br) * h ----
    {
        const float4 br0 = *(const float4*)(g_Bf + HIDD + c0);
        const float4 br1 = *(const float4*)(g_Bf + HIDD + c0 + 4);
#pragma unroll
        for (int rr = 0; rr < 4; rr++) {
            const int r = rowbase + rr;
            float4 ha = *(const float4*)(As + r * ASTR + c0);
            float4 hb = *(const float4*)(As + r * ASTR + c0 + 4);
            float v0, v1, v2, v3, v4, v5, v6, v7;
            upk2(racc[rr][0], v0, v1); upk2(racc[rr][1], v2, v3);
            upk2(racc[rr][2], v4, v5); upk2(racc[rr][3], v6, v7);
            float4 ca, cb;
            ca.x = fsig(v0 + br0.x) * ha.x;  ca.y = fsig(v1 + br0.y) * ha.y;
            ca.z = fsig(v2 + br0.z) * ha.z;  ca.w = fsig(v3 + br0.w) * ha.w;
            cb.x = fsig(v4 + br1.x) * hb.x;  cb.y = fsig(v5 + br1.y) * hb.y;
            cb.z = fsig(v6 + br1.z) * hb.z;  cb.w = fsig(v7 + br1.w) * hb.w;
            *(float4*)(Ac + r * ASTR + c0) = ca;
            *(float4*)(Ac + r * ASTR + c0 + 4) = cb;
        }
    }
    __syncwarp();

    // ---- phase 2: hc GEMM over candidate ----
    unsigned long long cacc[4][4];
#pragma unroll
    for (int rr = 0; rr < 4; rr++)
#pragma unroll
        for (int q = 0; q < 4; q++) cacc[rr][q] = 0ull;

#pragma unroll 2
    for (int j4 = 0; j4 < 16; ++j4) {
        float av[4][4];
#pragma unroll
        for (int rr = 0; rr < 4; rr++) {
            float4 q = *(const float4*)(Ac + (rowbase + rr) * ASTR + j4 * 4);
            av[rr][0] = q.x; av[rr][1] = q.y; av[rr][2] = q.z; av[rr][3] = q.w;
        }
#pragma unroll
        for (int k = 0; k < 4; ++k) {
            const int j = j4 * 4 + k;
            const ulonglong2* wcp = (const ulonglong2*)(Wc + j * HIDD + c0);
            const ulonglong2 w0 = wcp[0], w1 = wcp[1];
#pragma unroll
            for (int rr = 0; rr < 4; rr++) {
                const unsigned long long ap = pk2(av[rr][k], av[rr][k]);
                fma2(cacc[rr][0], ap, w0.x); fma2(cacc[rr][1], ap, w0.y);
                fma2(cacc[rr][2], ap, w1.x); fma2(cacc[rr][3], ap, w1.y);
            }
        }
    }
#pragma unroll
    for (int j = 64; j < 66; ++j) {
        const ulonglong2* wcp = (const ulonglong2*)(Wc + j * HIDD + c0);
        const ulonglong2 w0 = wcp[0], w1 = wcp[1];
#pragma unroll
        for (int rr = 0; rr < 4; rr++) {
            float a = Ac[(rowbase + rr) * ASTR + j];
            const unsigned long long ap = pk2(a, a);
            fma2(cacc[rr][0], ap, w0.x); fma2(cacc[rr][1], ap, w0.y);
            fma2(cacc[rr][2], ap, w1.x); fma2(cacc[rr][3], ap, w1.y);
        }
    }

    // ---- epilogue: out = z*h + (1-z)*hc, direct float4 stores ----
    {
        const float4 bz0 = *(const float4*)(g_Bf + c0);
        const float4 bz1 = *(const float4*)(g_Bf + c0 + 4);
        const float4 bc0 = *(const float4*)(g_Bf + 2 * HIDD + c0);
        const float4 bc1 = *(const float4*)(g_Bf + 2 * HIDD + c0 + 4);
#pragma unroll
        for (int rr = 0; rr < 4; rr++) {
            const int r = rowbase + rr;
            float4 ha = *(const float4*)(As + r * ASTR + c0);
            float4 hb = *(const float4*)(As + r * ASTR + c0 + 4);
            float z0, z1, z2, z3, z4, z5, z6, z7;
            float c0v, c1v, c2v, c3v, c4v, c5v, c6v, c7v;
            upk2(zacc[rr][0], z0, z1); upk2(zacc[rr][1], z2, z3);
            upk2(zacc[rr][2], z4, z5); upk2(zacc[rr][3], z6, z7);
            upk2(cacc[rr][0], c0v, c1v); upk2(cacc[rr][1], c2v, c3v);
            upk2(cacc[rr][2], c4v, c5v); upk2(cacc[rr][3], c6v, c7v);
            z0 = fsig(z0 + bz0.x); z1 = fsig(z1 + bz0.y);
            z2 = fsig(z2 + bz0.z); z3 = fsig(z3 + bz0.w);
            z4 = fsig(z4 + bz1.x); z5 = fsig(z5 + bz1.y);
            z6 = fsig(z6 + bz1.z); z7 = fsig(z7 + bz1.w);
            c0v = ftanh(c0v + bc0.x); c1v = ftanh(c1v + bc0.y);
            c2v = ftanh(c2v + bc0.z); c3v = ftanh(c3v + bc0.w);
            c4v = ftanh(c4v + bc1.x); c5v = ftanh(c5v + bc1.y);
            c6v = ftanh(c6v + bc1.z); c7v = ftanh(c7v + bc1.w);
            float4 oa, ob;
            oa.x = z0 * ha.x + (1.f - z0) * c0v;
            oa.y = z1 * ha.y + (1.f - z1) * c1v;
            oa.z = z2 * ha.z + (1.f - z2) * c2v;
            oa.w = z3 * ha.w + (1.f - z3) * c3v;
            ob.x = z4 * hb.x + (1.f - z4) * c4v;
            ob.y = z5 * hb.y + (1.f - z5) * c5v;
            ob.z = z6 * hb.z + (1.f - z6) * c6v;
            ob.w = z7 * hb.w + (1.f - z7) * c7v;
            *(float4*)(out + (size_t)(g0 + r) * HIDD + c0) = oa;
            *(float4*)(out + (size_t)(g0 + r) * HIDD + c0 + 4) = ob;
        }
    }
}

static const int SMEM_BYTES = (3 * CIN * HIDD + 2 * RPB * ASTR) * 4;  // 85504

extern "C" void kernel_launch(void* const* d_in, const int* in_sizes, int n_in,
                              void* d_out, int out_size) {
    (void)in_sizes; (void)n_in; (void)out_size;
    const float* x    = (const float*)d_in[0];    // [16,1024,2]
    const float* h0   = (const float*)d_in[1];    // [16,1024,64]
    const float* rnnW = (const float*)d_in[12];   // [6,198,64]
    const float* rnnb = (const float*)d_in[13];   // [6,64]
    float* out = (float*)d_out;                   // [16,1024,64]

    cudaFuncSetAttribute(dgcrm_main, cudaFuncAttributeMaxDynamicSharedMemorySize, SMEM_BYTES);

    fold_kernel<<<(3 * CIN * HIDD + 255) / 256, 256>>>(rnnW, rnnb);
    dgcrm_main<<<16384 / RPB, TPB, SMEM_BYTES>>>(x, h0, out);
}